// round 1
// baseline (speedup 1.0000x reference)
#include <cuda_runtime.h>

#define HH 224
#define WW 224
#define HW (HH * WW)
#define BB 256
#define NTOT (BB * HW)
#define NSTEPS 10
#define DT 0.15f

// Ping-pong state: sin(theta), cos(theta). Static device scratch (no allocs).
__device__ float g_sA[NTOT];
__device__ float g_cA[NTOT];
__device__ float g_sB[NTOT];
__device__ float g_cB[NTOT];

// theta0 = pi*(2x-1)  ->  s = sinpi(2x-1), c = cospi(2x-1)
__global__ void __launch_bounds__(256) init_kernel(const float* __restrict__ x,
                                                   float* __restrict__ s,
                                                   float* __restrict__ c) {
    int i = blockIdx.x * 256 + threadIdx.x;
    if (i < NTOT) {
        float t = 2.0f * x[i] - 1.0f;
        s[i] = sinpif(t);
        c[i] = cospif(t);
    }
}

// One Kuramoto step as a rotation of the (s,c) field.
// Block = one image row (224 threads). grid = (H, B).
__device__ __forceinline__ void step_body(const float* __restrict__ s_in,
                                          const float* __restrict__ c_in,
                                          const float* __restrict__ omega,
                                          float K,
                                          float& s_new, float& c_new,
                                          int& i_out, int& b_out) {
    const int b = blockIdx.y;
    const int y = blockIdx.x;
    const int x = threadIdx.x;
    const int i = b * HW + y * WW + x;

    float sc = s_in[i];
    float cc = c_in[i];

    float sn = 0.0f, cn = 0.0f;
    if (y > 0)      { sn += s_in[i - WW]; cn += c_in[i - WW]; }
    if (y < HH - 1) { sn += s_in[i + WW]; cn += c_in[i + WW]; }
    if (x > 0)      { sn += s_in[i - 1];  cn += c_in[i - 1];  }
    if (x < WW - 1) { sn += s_in[i + 1];  cn += c_in[i + 1];  }

    // sum_n sin(theta_n - theta) = cos*sn - sin*cn
    float coupling = fmaf(cc, sn, -sc * cn);
    float d = DT * (omega[y * WW + x] + K * coupling);

    // |d| <= 0.3: Taylor sin/cos (err ~1e-6, no MUFU)
    float d2 = d * d;
    float sd = d * fmaf(d2, fmaf(d2, (1.0f / 120.0f), (-1.0f / 6.0f)), 1.0f);
    float cd = fmaf(d2, fmaf(d2, (1.0f / 24.0f), -0.5f), 1.0f);

    s_new = fmaf(sc, cd, cc * sd);
    c_new = fmaf(cc, cd, -sc * sd);
    i_out = i;
    b_out = b;
}

__global__ void __launch_bounds__(WW) step_kernel(const float* __restrict__ s_in,
                                                  const float* __restrict__ c_in,
                                                  float* __restrict__ s_out,
                                                  float* __restrict__ c_out,
                                                  const float* __restrict__ omega,
                                                  const float* __restrict__ Kp) {
    float s_new, c_new;
    int i, b;
    step_body(s_in, c_in, omega, Kp[0], s_new, c_new, i, b);
    s_out[i] = s_new;
    c_out[i] = c_new;
}

// Final step writes directly into the output layout (B, [cos|sin], H, W) flattened.
__global__ void __launch_bounds__(WW) final_kernel(const float* __restrict__ s_in,
                                                   const float* __restrict__ c_in,
                                                   float* __restrict__ out,
                                                   const float* __restrict__ omega,
                                                   const float* __restrict__ Kp) {
    float s_new, c_new;
    int i, b;
    step_body(s_in, c_in, omega, Kp[0], s_new, c_new, i, b);
    int p = i - b * HW;                  // pixel index within image
    out[(long)b * (2 * HW) + p]       = c_new;   // cos channel
    out[(long)b * (2 * HW) + HW + p]  = s_new;   // sin channel
}

extern "C" void kernel_launch(void* const* d_in, const int* in_sizes, int n_in,
                              void* d_out, int out_size) {
    const float* x_img = (const float*)d_in[0];  // (B,1,H,W)
    const float* omega = (const float*)d_in[1];  // (1,1,H,W)
    const float* Kp    = (const float*)d_in[2];  // scalar
    float* out = (float*)d_out;

    float* sA; float* cA; float* sB; float* cB;
    cudaGetSymbolAddress((void**)&sA, g_sA);
    cudaGetSymbolAddress((void**)&cA, g_cA);
    cudaGetSymbolAddress((void**)&sB, g_sB);
    cudaGetSymbolAddress((void**)&cB, g_cB);

    dim3 grid(HH, BB);
    dim3 block(WW);

    init_kernel<<<(NTOT + 255) / 256, 256>>>(x_img, sA, cA);

    // 9 ping-pong steps: A->B, B->A, ... (odd count ends in B)
    const float* si = sA; const float* ci = cA;
    float* so = sB; float* co = cB;
    for (int st = 0; st < NSTEPS - 1; st++) {
        step_kernel<<<grid, block>>>(si, ci, so, co, omega, Kp);
        const float* ts = so; const float* tc = co;
        so = (float*)si; co = (float*)ci;
        si = ts; ci = tc;
    }

    // 10th step -> output
    final_kernel<<<grid, block>>>(si, ci, out, omega, Kp);
}

// round 2
// speedup vs baseline: 1.8937x; 1.8937x over previous
#include <cuda_runtime.h>

#define HH 224
#define WW 224
#define HW (HH * WW)
#define BB 256
#define NTOT (BB * HW)
#define DTc 0.15f

#define TY 46                  // interior rows per tile
#define HALO 5                 // 5 fused steps per kernel
#define RR (TY + 2 * HALO)     // 56 data rows in smem
#define RP (RR + 2)            // +2 zero-pad rows
#define CW (WW + 2)            // +2 zero-pad cols
#define TILES 5                // 5*46 = 230 >= 224
#define NTHREADS 896           // 4 strips x 224 columns
#define STRIPS 4
#define ROWS_PER (RR / STRIPS) // 14 rows per thread
#define SMF (RP * CW)          // floats per smem array (13108)
#define SMEM_BYTES (4 * SMF * 4) // sA,cA,sB,cB = 209728 B

// Intermediate state between the two fused kernels (no allocs allowed).
__device__ float g_s[NTOT];
__device__ float g_c[NTOT];

// One Kuramoto step over the whole smem tile; column-sweep with
// register-carried up/center values. Pads (row 0, row RP-1, col 0, col CW-1)
// are zero and never written -> branch-free stencil; zero cells rotate to
// zero, so out-of-image cells stay exactly 0 (zero-pad semantics).
__device__ __forceinline__ void step_tile(const float* __restrict__ ps,
                                          const float* __restrict__ pc,
                                          float* __restrict__ qs,
                                          float* __restrict__ qc,
                                          const float* __restrict__ dto,
                                          float DTK, int r0, int xc) {
    int idx = r0 * CW + xc;
    float s_up = ps[idx - CW], c_up = pc[idx - CW];
    float s_c  = ps[idx],      c_c  = pc[idx];
#pragma unroll
    for (int j = 0; j < ROWS_PER; j++) {
        float s_dn = ps[idx + CW];
        float c_dn = pc[idx + CW];
        float s_l = ps[idx - 1], s_r = ps[idx + 1];
        float c_l = pc[idx - 1], c_r = pc[idx + 1];

        float sn = (s_up + s_dn) + (s_l + s_r);
        float cn = (c_up + c_dn) + (c_l + c_r);

        // coupling = cos*sn - sin*cn
        float t2 = s_c * cn;
        float coupling = fmaf(c_c, sn, -t2);
        float d = fmaf(DTK, coupling, dto[j]);

        // |d| <= 0.3: Taylor sin/cos, err ~4e-8
        float d2 = d * d;
        float sd = d * fmaf(d2, fmaf(d2, 8.3333333e-3f, -0.16666667f), 1.0f);
        float cd = fmaf(d2, fmaf(d2, 4.1666668e-2f, -0.5f), 1.0f);

        float a = c_c * sd;
        float e = s_c * sd;
        qs[idx] = fmaf(s_c, cd, a);
        qc[idx] = fmaf(c_c, cd, -e);

        s_up = s_c; c_up = c_c;
        s_c = s_dn; c_c = c_dn;
        idx += CW;
    }
}

template <int PHASE>  // 0: init from x_img, write g_s/g_c ; 1: read g_s/g_c, write out
__global__ void __launch_bounds__(NTHREADS, 1)
fused5_kernel(const float* __restrict__ x_img,
              const float* __restrict__ omega,
              const float* __restrict__ Kp,
              float* __restrict__ out) {
    extern __shared__ float sm[];
    float* sA = sm;
    float* cA = sm + SMF;
    float* sB = sm + 2 * SMF;
    float* cB = sm + 3 * SMF;

    const int tid = threadIdx.x;
    const int x = tid % WW;            // column 0..223
    const int strip = tid / WW;        // 0..3
    const int r0 = 1 + strip * ROWS_PER;
    const int xc = x + 1;
    const int b = blockIdx.y;
    const int y0 = blockIdx.x * TY;
    const float DTK = DTc * Kp[0];

    // Zero everything (pads + out-of-image rows must be 0).
    for (int i = tid; i < 4 * SMF; i += NTHREADS) sm[i] = 0.0f;
    __syncthreads();

    // Per-row DT*omega (0 outside image) + load initial state into bufA.
    float dto[ROWS_PER];
#pragma unroll
    for (int j = 0; j < ROWS_PER; j++) {
        int r = r0 + j;
        int gy = y0 - HALO + (r - 1);
        bool in = (gy >= 0) && (gy < HH);
        dto[j] = in ? DTc * omega[gy * WW + x] : 0.0f;
        if (in) {
            int gi = b * HW + gy * WW + x;
            float s, c;
            if (PHASE == 0) {
                float t = fmaf(2.0f, x_img[gi], -1.0f);
                sincospif(t, &s, &c);
            } else {
                s = g_s[gi];
                c = g_c[gi];
            }
            sA[r * CW + xc] = s;
            cA[r * CW + xc] = c;
        }
    }
    __syncthreads();

    // 5 fused steps, ping-pong A<->B. After 5 steps result is in (sB,cB).
    const float* ps = sA; const float* pc = cA;
    float* qs = sB; float* qc = cB;
#pragma unroll
    for (int st = 0; st < HALO; st++) {
        step_tile(ps, pc, qs, qc, dto, DTK, r0, xc);
        __syncthreads();
        const float* ts = qs; const float* tc = qc;
        qs = (float*)ps; qc = (float*)pc;
        ps = ts; pc = tc;
    }
    // Result now in (ps,pc).

    // Write back interior rows (r in [HALO+1, HALO+TY]).
#pragma unroll
    for (int j = 0; j < ROWS_PER; j++) {
        int r = r0 + j;
        if (r >= 1 + HALO && r <= HALO + TY) {
            int gy = y0 + (r - 1 - HALO);
            if (gy < HH) {
                float s = ps[r * CW + xc];
                float c = pc[r * CW + xc];
                if (PHASE == 0) {
                    int gi = b * HW + gy * WW + x;
                    g_s[gi] = s;
                    g_c[gi] = c;
                } else {
                    int p = gy * WW + x;
                    out[(long)b * (2 * HW) + p] = c;       // cos channel
                    out[(long)b * (2 * HW) + HW + p] = s;  // sin channel
                }
            }
        }
    }
}

extern "C" void kernel_launch(void* const* d_in, const int* in_sizes, int n_in,
                              void* d_out, int out_size) {
    const float* x_img = (const float*)d_in[0];  // (B,1,H,W)
    const float* omega = (const float*)d_in[1];  // (1,1,H,W)
    const float* Kp    = (const float*)d_in[2];  // scalar
    float* out = (float*)d_out;

    static bool configured = false;
    if (!configured) {
        cudaFuncSetAttribute(fused5_kernel<0>,
                             cudaFuncAttributeMaxDynamicSharedMemorySize, SMEM_BYTES);
        cudaFuncSetAttribute(fused5_kernel<1>,
                             cudaFuncAttributeMaxDynamicSharedMemorySize, SMEM_BYTES);
        configured = true;
    }

    dim3 grid(TILES, BB);
    dim3 block(NTHREADS);
    fused5_kernel<0><<<grid, block, SMEM_BYTES>>>(x_img, omega, Kp, out);
    fused5_kernel<1><<<grid, block, SMEM_BYTES>>>(x_img, omega, Kp, out);
}

// round 3
// speedup vs baseline: 2.0710x; 1.0936x over previous
#include <cuda_runtime.h>

#define HH 224
#define WW 224
#define HW (HH * WW)
#define BB 256
#define NTOT (BB * HW)
#define DTc 0.15f

#define TY 46                  // interior rows per tile
#define HALO 5                 // 5 fused steps per kernel
#define RR (TY + 2 * HALO)     // 56 data rows in tile
#define RPAIRS (RR / 2)        // 28 data row-pairs (packs)
#define RPP (RPAIRS + 2)       // +2 zero-pad pack rows -> 30
#define PWP (WW + 2)           // pack-row width in packs (226, incl col pads)
#define TILES 5                // 5*46 = 230 >= 224
#define NTHREADS 896           // 4 strips x 224 columns
#define STRIPS 4
#define PACKS_PER (RPAIRS / STRIPS)  // 7 packs per thread
#define SMP (RPP * PWP)        // ulonglong2 cells per buffer (6780)
#define SMEM_BYTES (2 * SMP * 16)    // two ping-pong buffers = 216960 B

typedef unsigned long long u64;

// Intermediate state between the two fused kernels (no allocs allowed).
__device__ float g_s[NTOT];
__device__ float g_c[NTOT];

// ---- packed f32x2 helpers ----
__device__ __forceinline__ u64 pk2(float lo, float hi) {
    u64 r; asm("mov.b64 %0, {%1, %2};" : "=l"(r) : "f"(lo), "f"(hi)); return r;
}
__device__ __forceinline__ void unpk2(u64 v, float& lo, float& hi) {
    asm("mov.b64 {%0, %1}, %2;" : "=f"(lo), "=f"(hi) : "l"(v));
}
// (a.hi, b.lo)
__device__ __forceinline__ u64 funnel(u64 a, u64 b) {
    u64 r;
    asm("{\n\t.reg .f32 al, ah, bl, bh;\n\t"
        "mov.b64 {al, ah}, %1;\n\t"
        "mov.b64 {bl, bh}, %2;\n\t"
        "mov.b64 %0, {ah, bl};\n\t}"
        : "=l"(r) : "l"(a), "l"(b));
    return r;
}
__device__ __forceinline__ u64 add2(u64 a, u64 b) {
    u64 d; asm("add.rn.f32x2 %0, %1, %2;" : "=l"(d) : "l"(a), "l"(b)); return d;
}
__device__ __forceinline__ u64 mul2(u64 a, u64 b) {
    u64 d; asm("mul.rn.f32x2 %0, %1, %2;" : "=l"(d) : "l"(a), "l"(b)); return d;
}
__device__ __forceinline__ u64 fma2(u64 a, u64 b, u64 c) {
    u64 d; asm("fma.rn.f32x2 %0, %1, %2, %3;" : "=l"(d) : "l"(a), "l"(b), "l"(c)); return d;
}
__device__ __forceinline__ u64 neg2(u64 a) { return a ^ 0x8000000080000000ULL; }

template <int PHASE>  // 0: init from x_img, write g_s/g_c ; 1: read g_s/g_c, write out
__global__ void __launch_bounds__(NTHREADS, 1)
fused5_kernel(const float* __restrict__ x_img,
              const float* __restrict__ omega,
              const float* __restrict__ Kp,
              float* __restrict__ out) {
    extern __shared__ ulonglong2 sm2[];
    ulonglong2* bufA = sm2;
    ulonglong2* bufB = sm2 + SMP;

    const int tid = threadIdx.x;
    const int x = tid % WW;            // column 0..223 (warps stay in one strip: 224=7 warps)
    const int strip = tid / WW;        // 0..3
    const int r0p = 1 + strip * PACKS_PER;  // first data pack row for this thread
    const int xc = x + 1;
    const int b = blockIdx.y;
    const int y0 = blockIdx.x * TY;
    const float DTK = DTc * Kp[0];
    const u64 DTK2 = pk2(DTK, DTK);
    const u64 ONE2 = pk2(1.0f, 1.0f);
    const u64 C3 = pk2(-1.0f / 6.0f, -1.0f / 6.0f);
    const u64 C5 = pk2(8.3333333e-3f, 8.3333333e-3f);
    const u64 C2 = pk2(-0.5f, -0.5f);
    const u64 C4 = pk2(4.1666668e-2f, 4.1666668e-2f);

    // Zero both buffers (pads + out-of-image rows must be exactly 0).
    for (int i = tid; i < 2 * SMP; i += NTHREADS) sm2[i] = make_ulonglong2(0ULL, 0ULL);
    __syncthreads();

    // Per-pack DT*omega (0 outside image) + load initial state into bufA.
    u64 dto2[PACKS_PER];
#pragma unroll
    for (int j = 0; j < PACKS_PER; j++) {
        const int rp = r0p + j;
        const int rt0 = 2 * (rp - 1);          // tile row of lo element
        const int gy0 = y0 - HALO + rt0;
        const int gy1 = gy0 + 1;
        const bool in0 = (gy0 >= 0) && (gy0 < HH);
        const bool in1 = (gy1 >= 0) && (gy1 < HH);
        float o0 = in0 ? DTc * omega[gy0 * WW + x] : 0.0f;
        float o1 = in1 ? DTc * omega[gy1 * WW + x] : 0.0f;
        dto2[j] = pk2(o0, o1);

        float s0 = 0.0f, c0 = 0.0f, s1 = 0.0f, c1 = 0.0f;
        if (PHASE == 0) {
            if (in0) sincospif(fmaf(2.0f, x_img[b * HW + gy0 * WW + x], -1.0f), &s0, &c0);
            if (in1) sincospif(fmaf(2.0f, x_img[b * HW + gy1 * WW + x], -1.0f), &s1, &c1);
        } else {
            if (in0) { s0 = g_s[b * HW + gy0 * WW + x]; c0 = g_c[b * HW + gy0 * WW + x]; }
            if (in1) { s1 = g_s[b * HW + gy1 * WW + x]; c1 = g_c[b * HW + gy1 * WW + x]; }
        }
        bufA[rp * PWP + xc] = make_ulonglong2(pk2(s0, s1), pk2(c0, c1));
    }
    __syncthreads();

    // 5 fused steps, ping-pong A<->B.
    const ulonglong2* p = bufA;
    ulonglong2* q = bufB;
#pragma unroll
    for (int st = 0; st < HALO; st++) {
        int idx = r0p * PWP + xc;
        ulonglong2 prev = p[idx - PWP];
        ulonglong2 cur = p[idx];
#pragma unroll
        for (int j = 0; j < PACKS_PER; j++) {
            ulonglong2 nxt = p[idx + PWP];
            ulonglong2 lft = p[idx - 1];
            ulonglong2 rgt = p[idx + 1];

            u64 up_s = funnel(prev.x, cur.x);
            u64 up_c = funnel(prev.y, cur.y);
            u64 dn_s = funnel(cur.x, nxt.x);
            u64 dn_c = funnel(cur.y, nxt.y);

            u64 sn = add2(add2(up_s, dn_s), add2(lft.x, rgt.x));
            u64 cn = add2(add2(up_c, dn_c), add2(lft.y, rgt.y));

            // coupling = cos*sn - sin*cn
            u64 coup = fma2(cur.y, sn, neg2(mul2(cur.x, cn)));
            u64 d = fma2(DTK2, coup, dto2[j]);

            // |d| <= 0.3: Taylor sin/cos, err ~4e-8
            u64 d2 = mul2(d, d);
            u64 sd = mul2(d, fma2(d2, fma2(d2, C5, C3), ONE2));
            u64 cd = fma2(d2, fma2(d2, C4, C2), ONE2);

            u64 ns = fma2(cur.x, cd, mul2(cur.y, sd));
            u64 nc = fma2(cur.y, cd, neg2(mul2(cur.x, sd)));
            q[idx] = make_ulonglong2(ns, nc);

            prev = cur;
            cur = nxt;
            idx += PWP;
        }
        __syncthreads();
        const ulonglong2* t = q;
        q = (ulonglong2*)p;
        p = t;
    }
    // Result now in p.

    // Write back interior rows (tile rows HALO..HALO+TY-1 = 5..50).
#pragma unroll
    for (int j = 0; j < PACKS_PER; j++) {
        const int rp = r0p + j;
        ulonglong2 v = p[rp * PWP + xc];
        float s0, s1, c0, c1;
        unpk2(v.x, s0, s1);
        unpk2(v.y, c0, c1);
        const int rt0 = 2 * (rp - 1);
#pragma unroll
        for (int par = 0; par < 2; par++) {
            const int rt = rt0 + par;
            if (rt >= HALO && rt < HALO + TY) {
                const int gy = y0 + (rt - HALO);
                if (gy < HH) {
                    const float s = par ? s1 : s0;
                    const float c = par ? c1 : c0;
                    if (PHASE == 0) {
                        const int gi = b * HW + gy * WW + x;
                        g_s[gi] = s;
                        g_c[gi] = c;
                    } else {
                        const int pix = gy * WW + x;
                        out[(long)b * (2 * HW) + pix] = c;       // cos channel
                        out[(long)b * (2 * HW) + HW + pix] = s;  // sin channel
                    }
                }
            }
        }
    }
}

extern "C" void kernel_launch(void* const* d_in, const int* in_sizes, int n_in,
                              void* d_out, int out_size) {
    const float* x_img = (const float*)d_in[0];  // (B,1,H,W)
    const float* omega = (const float*)d_in[1];  // (1,1,H,W)
    const float* Kp    = (const float*)d_in[2];  // scalar
    float* out = (float*)d_out;

    static bool configured = false;
    if (!configured) {
        cudaFuncSetAttribute(fused5_kernel<0>,
                             cudaFuncAttributeMaxDynamicSharedMemorySize, SMEM_BYTES);
        cudaFuncSetAttribute(fused5_kernel<1>,
                             cudaFuncAttributeMaxDynamicSharedMemorySize, SMEM_BYTES);
        configured = true;
    }

    dim3 grid(TILES, BB);
    dim3 block(NTHREADS);
    fused5_kernel<0><<<grid, block, SMEM_BYTES>>>(x_img, omega, Kp, out);
    fused5_kernel<1><<<grid, block, SMEM_BYTES>>>(x_img, omega, Kp, out);
}